// round 10
// baseline (speedup 1.0000x reference)
#include <cuda_runtime.h>

#define NLAB   2047
#define NBATCH 2048
#define RPC    4          // batch rows per CTA

// Precomputed EXP of compact transition tables (gathered per launch, deterministic).
__device__ float4 g_eTup[2048];   // exp T for edge n -> parent(n)
__device__ float4 g_eTdn[2048];   // exp T for edge parent(n) -> n

__global__ void prep_kernel(const float* __restrict__ trans) {
    int n = blockIdx.x * blockDim.x + threadIdx.x;
    if (n >= NLAB) return;
    if (n == 0) {
        g_eTup[0] = make_float4(1.f, 1.f, 1.f, 1.f);
        g_eTdn[0] = make_float4(1.f, 1.f, 1.f, 1.f);
        return;
    }
    int p = (n - 1) >> 1;
    const float4* t4 = reinterpret_cast<const float4*>(trans);
    float4 u = t4[(size_t)p * NLAB + n];
    float4 d = t4[(size_t)n * NLAB + p];
    g_eTup[n] = make_float4(__expf(u.x), __expf(u.y), __expf(u.z), __expf(u.w));
    g_eTdn[n] = make_float4(__expf(d.x), __expf(d.y), __expf(d.z), __expf(d.w));
}

__device__ __forceinline__ float2 f2add(float2 a, float2 b) {
    return make_float2(a.x + b.x, a.y + b.y);
}

__device__ __forceinline__ float2 lsepair2(float2 x, float4 eT) {
    float m  = fmaxf(x.x, x.y);
    float pd = __expf(fminf(x.x, x.y) - m);
    bool  f  = (x.x >= x.y);
    float a0 = f ? eT.x : eT.y, b0 = f ? eT.y : eT.x;
    float a1 = f ? eT.z : eT.w, b1 = f ? eT.w : eT.z;
    return make_float2(m + __logf(fmaf(pd, b0, a0)),
                       m + __logf(fmaf(pd, b1, a1)));
}

__device__ __forceinline__ float2 up_combine(float2 xl, float2 xr, float4 Tl, float4 Tr) {
    float2 a = lsepair2(xl, Tl);
    float2 b = lsepair2(xr, Tr);
    return make_float2(a.x + b.x, a.y + b.y);
}

__device__ __forceinline__ float lse2(float u, float v) {
    float m = fmaxf(u, v);
    return m + __logf(1.0f + __expf(fminf(u, v) - m));
}

__device__ __forceinline__ void emit2(float* __restrict__ orow, int n, float2 s) {
    float z = lse2(s.x, s.y);
    orow[n]        = s.x - z;
    orow[NLAB + n] = s.y - z;
}

__device__ __forceinline__ float2 ld_e(const float* __restrict__ er, int n) {
    return make_float2(er[n], er[NLAB + n]);
}

#define PARENT_EXP(tp, m, pd, f) \
    float m  = fmaxf((tp).x, (tp).y); \
    float pd = __expf(fminf((tp).x, (tp).y) - m); \
    bool  f  = ((tp).x >= (tp).y);

__device__ __forceinline__ float2 child_be(float m, float pd, bool f, float4 eT) {
    float a0 = f ? eT.x : eT.y, b0 = f ? eT.y : eT.x;
    float a1 = f ? eT.z : eT.w, b1 = f ? eT.w : eT.z;
    return make_float2(m + __logf(fmaf(pd, b0, a0)),
                       m + __logf(fmaf(pd, b1, a1)));
}

// two-level up: thread owns q; computes alpha of q's two children then alpha[q]
__device__ __forceinline__ void up2(float2* __restrict__ E, float2* __restrict__ A, int q) {
    int cl = 2 * q + 1, cr = cl + 1;
    int gl = 2 * cl + 1, gr = 2 * cr + 1;
    float2 Acl = up_combine(f2add(E[gl], A[gl]), f2add(E[gl + 1], A[gl + 1]),
                            g_eTup[gl], g_eTup[gl + 1]);
    float2 Acr = up_combine(f2add(E[gr], A[gr]), f2add(E[gr + 1], A[gr + 1]),
                            g_eTup[gr], g_eTup[gr + 1]);
    A[cl] = Acl; A[cr] = Acr;
    A[q] = up_combine(f2add(E[cl], Acl), f2add(E[cr], Acr), g_eTup[cl], g_eTup[cr]);
}

// two-level down: q has final t in E[q]; emit children+grandchildren, E <- t
__device__ __forceinline__ void down2(float2* __restrict__ E, float2* __restrict__ A,
                                      float* __restrict__ orow, int q) {
    float2 tq = E[q];
    PARENT_EXP(tq, m, pd, f)
    #pragma unroll
    for (int j = 0; j < 2; ++j) {
        int c = 2 * q + 1 + j;
        float2 be = child_be(m, pd, f, g_eTdn[c]);
        float2 Ec = E[c];
        emit2(orow, c, f2add(f2add(Ec, A[c]), be));
        float2 tc = f2add(Ec, be);
        E[c] = tc;
        PARENT_EXP(tc, m2, pd2, f2)
        #pragma unroll
        for (int k = 0; k < 2; ++k) {
            int g = 2 * c + 1 + k;
            float2 be2 = child_be(m2, pd2, f2, g_eTdn[g]);
            float2 Eg = E[g];
            emit2(orow, g, f2add(f2add(Eg, A[g]), be2));
            E[g] = f2add(Eg, be2);
        }
    }
}

// 4 rows per CTA, dynamic smem 64 KB: E[4][1024] then A[4][1024] (float2).
// 6 block barriers; L1..L4 handled entirely by warp 0 with __syncwarp.
__global__ void __launch_bounds__(256, 3) crf_kernel(const float* __restrict__ em,
                                                     float* __restrict__ out) {
    extern __shared__ float2 sm[];
    float2* Eb = sm;            // 4096 float2
    float2* Ab = sm + 4096;     // 4096 float2

    const int tid = threadIdx.x;
    const size_t rowbase = (size_t)blockIdx.x * RPC * (2 * NLAB);

    // ---- P1: load internal emissions + alpha of leaf-parents (L9)
    #pragma unroll 1
    for (int r = 0; r < RPC; ++r) {
        const float* __restrict__ er = em + rowbase + (size_t)r * (2 * NLAB);
        float2* E = Eb + (r << 10);
        float2* A = Ab + (r << 10);
        for (int n = tid; n < 1023; n += 256) E[n] = ld_e(er, n);
        for (int i = tid; i < 512; i += 256) {
            int p = 511 + i, k = 2 * p + 1;
            A[p] = up_combine(ld_e(er, k), ld_e(er, k + 1), g_eTup[k], g_eTup[k + 1]);
        }
    }
    __syncthreads();                                            // barrier 1

    // ---- P2: up L8+L7 (own L7 node), 128 x 4 = 512 tasks
    #pragma unroll
    for (int it = 0; it < 2; ++it) {
        int idx = tid + 256 * it;
        int r = idx >> 7, i = idx & 127;
        up2(Eb + (r << 10), Ab + (r << 10), 127 + i);
    }
    __syncthreads();                                            // barrier 2

    // ---- P3: up L6+L5 (own L5 node), 32 x 4 = 128 tasks
    if (tid < 128) {
        int r = tid >> 5, i = tid & 31;
        up2(Eb + (r << 10), Ab + (r << 10), 31 + i);
    }
    __syncthreads();                                            // barrier 3

    // ---- warp-0 section: L4..root..L4 (all four rows)
    if (tid < 32) {
        {   // P4: up L4+L3 (own L3), 8 x 4 = 32 tasks
            int r = tid >> 3, i = tid & 7;
            up2(Eb + (r << 10), Ab + (r << 10), 7 + i);
        }
        __syncwarp();
        if (tid < 8) {   // P5: up L2+L1 (own L1), 2 x 4 = 8 tasks
            int r = tid >> 1, i = tid & 1;
            up2(Eb + (r << 10), Ab + (r << 10), 1 + i);
        }
        __syncwarp();
        if (tid < RPC) { // P6: root emit + down L1,L2 (one thread per row)
            int r = tid;
            float2* E = Eb + (r << 10);
            float2* A = Ab + (r << 10);
            float* __restrict__ orow = out + rowbase + (size_t)r * (2 * NLAB);
            float2 x1 = f2add(E[1], A[1]), x2 = f2add(E[2], A[2]);
            float2 a0 = up_combine(x1, x2, g_eTup[1], g_eTup[2]);
            emit2(orow, 0, f2add(E[0], a0));
            float2 t0 = E[0];                       // beta(root)=0
            PARENT_EXP(t0, m, pd, f)
            #pragma unroll
            for (int j = 1; j <= 2; ++j) {
                float2 be = child_be(m, pd, f, g_eTdn[j]);
                emit2(orow, j, f2add(f2add(E[j], A[j]), be));
                float2 tj = f2add(E[j], be);
                E[j] = tj;
                PARENT_EXP(tj, m2, pd2, f2)
                #pragma unroll
                for (int k = 0; k < 2; ++k) {
                    int n2 = 2 * j + 1 + k;
                    float2 be2 = child_be(m2, pd2, f2, g_eTdn[n2]);
                    emit2(orow, n2, f2add(f2add(E[n2], A[n2]), be2));
                    E[n2] = f2add(E[n2], be2);
                }
            }
        }
        __syncwarp();
        if (tid < 16) {  // P7: down L3+L4 (own L2 node), 4 x 4 = 16 tasks
            int r = tid >> 2, i = tid & 3;
            down2(Eb + (r << 10), Ab + (r << 10),
                  out + rowbase + (size_t)r * (2 * NLAB), 3 + i);
        }
    }
    __syncthreads();                                            // barrier 4

    // ---- P8: down L5+L6 (own L4 node), 16 x 4 = 64 tasks
    if (tid < 64) {
        int r = tid >> 4, i = tid & 15;
        down2(Eb + (r << 10), Ab + (r << 10),
              out + rowbase + (size_t)r * (2 * NLAB), 15 + i);
    }
    __syncthreads();                                            // barrier 5

    // ---- P9: down L7+L8 (own L6 node), 64 x 4 = 256 tasks
    {
        int r = tid >> 6, i = tid & 63;
        down2(Eb + (r << 10), Ab + (r << 10),
              out + rowbase + (size_t)r * (2 * NLAB), 63 + i);
    }
    __syncthreads();                                            // barrier 6

    // ---- P10: down L9 + leaves (own L8 node), 256 x 4 = 1024 tasks
    #pragma unroll
    for (int it = 0; it < RPC; ++it) {
        int idx = tid + 256 * it;
        int r = idx >> 8, i = idx & 255;
        float2* E = Eb + (r << 10);
        float2* A = Ab + (r << 10);
        const float* __restrict__ er = em + rowbase + (size_t)r * (2 * NLAB);
        float* __restrict__ orow = out + rowbase + (size_t)r * (2 * NLAB);
        int q = 255 + i;
        float2 tq = E[q];
        PARENT_EXP(tq, m, pd, f)
        #pragma unroll
        for (int j = 0; j < 2; ++j) {
            int c = 2 * q + 1 + j;                 // L9
            float2 be = child_be(m, pd, f, g_eTdn[c]);
            float2 Ec = E[c];
            emit2(orow, c, f2add(f2add(Ec, A[c]), be));
            float2 tc = f2add(Ec, be);
            PARENT_EXP(tc, m2, pd2, f2)
            #pragma unroll
            for (int k = 0; k < 2; ++k) {
                int g = 2 * c + 1 + k;             // leaf
                float2 be2 = child_be(m2, pd2, f2, g_eTdn[g]);
                emit2(orow, g, f2add(ld_e(er, g), be2));   // leaf alpha = 0
            }
        }
    }
}

extern "C" void kernel_launch(void* const* d_in, const int* in_sizes, int n_in,
                              void* d_out, int out_size) {
    const float* em = (const float*)d_in[0];
    const float* tr = (const float*)d_in[1];
    if (n_in >= 2 && in_sizes[0] != NBATCH * 2 * NLAB) {
        em = (const float*)d_in[1];
        tr = (const float*)d_in[0];
    }
    cudaFuncSetAttribute(crf_kernel, cudaFuncAttributeMaxDynamicSharedMemorySize,
                         8192 * sizeof(float2));
    prep_kernel<<<(NLAB + 255) / 256, 256>>>(tr);
    crf_kernel<<<NBATCH / RPC, 256, 8192 * sizeof(float2)>>>(em, (float*)d_out);
}